// round 8
// baseline (speedup 1.0000x reference)
#include <cuda_runtime.h>
#include <cuda_bf16.h>
#include <cstdint>

#define NTH 256
#define STAGES 3

// ---------------- scratch (device globals; allocation-free) ----------------
__device__ __nv_bfloat16 g_xt[22937600];   // XT per level: [bat][n][k], k contiguous
__device__ __nv_bfloat16 g_wb[478464];     // W bf16: w0@0, w1@68352, w2@205056

__constant__ float g_anch[3][6] = {
    {10.f, 13.f, 16.f, 30.f, 33.f, 23.f},
    {30.f, 61.f, 62.f, 45.f, 59.f, 119.f},
    {116.f, 90.f, 156.f, 198.f, 373.f, 326.f}
};

__device__ __forceinline__ float sigm(float x) { return 1.f / (1.f + __expf(-x)); }

__device__ __forceinline__ void mma_bf16(float* c, const uint32_t* a, const uint32_t* b) {
    asm volatile(
        "mma.sync.aligned.m16n8k16.row.col.f32.bf16.bf16.f32 "
        "{%0,%1,%2,%3}, {%4,%5,%6,%7}, {%8,%9}, {%0,%1,%2,%3};"
        : "+f"(c[0]), "+f"(c[1]), "+f"(c[2]), "+f"(c[3])
        : "r"(a[0]), "r"(a[1]), "r"(a[2]), "r"(a[3]), "r"(b[0]), "r"(b[1]));
}
__device__ __forceinline__ void ldsm4(uint32_t* r, uint32_t addr) {
    asm volatile("ldmatrix.sync.aligned.m8n8.x4.shared.b16 {%0,%1,%2,%3}, [%4];"
                 : "=r"(r[0]), "=r"(r[1]), "=r"(r[2]), "=r"(r[3]) : "r"(addr));
}
__device__ __forceinline__ void cp16(uint32_t saddr, const void* gptr, uint32_t sz) {
    asm volatile("cp.async.cg.shared.global [%0], [%1], 16, %2;"
                 :: "r"(saddr), "l"(gptr), "r"(sz) : "memory");
}
#define CP_COMMIT() asm volatile("cp.async.commit_group;" ::: "memory")
#define CP_WAIT()   asm volatile("cp.async.wait_group %0;" :: "n"(STAGES - 2) : "memory")

// row = 64 data halves + 8 pad = 72 halves = 144 bytes (16B-aligned; bank shift 4/row)
#define ROW_BYTES 144
#define MAT_BYTES (128 * ROW_BYTES)            // 18432 per matrix
#define STAGE_BYTES (2 * MAT_BYTES)            // 36864 (A then B)
#define DYN_BYTES (STAGES * STAGE_BYTES + 1072)

// ---------------- convert kernels ----------------
__global__ void convert_w(const float* __restrict__ w0, const float* __restrict__ w1,
                          const float* __restrict__ w2)
{
    int i = blockIdx.x * 256 + threadIdx.x;
    if (i < 68352)        g_wb[i] = __float2bfloat16(w0[i]);
    else if (i < 205056)  g_wb[i] = __float2bfloat16(w1[i - 68352]);
    else if (i < 478464)  g_wb[i] = __float2bfloat16(w2[i - 205056]);
}

template<int C, int HW>
__global__ void transpose_x(const float* __restrict__ X, __nv_bfloat16* __restrict__ XT)
{
    __shared__ float t[32][33];
    const int n0 = blockIdx.x * 32, k0 = blockIdx.y * 32, bat = blockIdx.z;
    const int tx = threadIdx.x, ty = threadIdx.y;
    const float* Xb = X + (size_t)bat * C * HW;
#pragma unroll
    for (int r = 0; r < 32; r += 8) {
        const int n = n0 + tx;
        t[ty + r][tx] = (n < HW) ? Xb[(size_t)(k0 + ty + r) * HW + n] : 0.f;
    }
    __syncthreads();
    __nv_bfloat16* XTb = XT + (size_t)bat * HW * C;
#pragma unroll
    for (int r = 0; r < 32; r += 8) {
        const int n = n0 + ty + r;
        if (n < HW) XTb[(size_t)n * C + k0 + tx] = __float2bfloat16(t[tx][ty + r]);
    }
}

// ---------------- GEMM + decode ----------------
template<int C, int HW, int NX>
__device__ __forceinline__ void run_level(
    const __nv_bfloat16* __restrict__ XT, const __nv_bfloat16* __restrict__ Wb,
    const float* __restrict__ Bias, float* __restrict__ Out,
    int bat, int mt, int nt, float stride_px, int lvl, int loff)
{
    extern __shared__ char sh[];
    float* sBias = (float*)(sh + STAGES * STAGE_BYTES);
    const uint32_t shBase = (uint32_t)__cvta_generic_to_shared(sh);

    const int tid  = threadIdx.x;
    const int wid  = tid >> 5;
    const int lane = tid & 31;
    const int g    = lane >> 2;
    const int t4   = lane & 3;
    const int wm   = (wid & 1) * 64;
    const int wn   = (wid >> 1) * 32;
    const int m0   = mt * 128;
    const int n0   = nt * 128;
    const __nv_bfloat16* XTb = XT + (size_t)bat * HW * C;

    for (int i = tid; i < 267; i += NTH) sBias[i] = Bias[i];

    // ---- cp.async loader: thread t -> one 128-byte row (A if t<128, else B) ----
    const bool isB = tid >= 128;
    const int lRow = tid & 127;
    const uint32_t lSz = isB ? (((n0 + lRow) < HW) ? 16u : 0u)
                             : (((m0 + lRow) < 267) ? 16u : 0u);
    const __nv_bfloat16* gRow = isB
        ? XTb + (size_t)((n0 + lRow) < HW ? (n0 + lRow) : 0) * C
        : Wb  + (size_t)((m0 + lRow) < 267 ? (m0 + lRow) : 0) * C;
    const uint32_t sRow = shBase + (isB ? MAT_BYTES : 0) + lRow * ROW_BYTES;

    const int NCH = C / 64;
#pragma unroll
    for (int s = 0; s < STAGES - 1; ++s) {
        if (s < NCH) {
#pragma unroll
            for (int q = 0; q < 8; ++q)
                cp16(sRow + s * STAGE_BYTES + q * 16, gRow + (size_t)s * 64 + q * 8, lSz);
        }
        CP_COMMIT();
    }

    // ---- ldmatrix lane addressing ----
    // A x4: lanes 0-15 -> m rows (wm+ma*16 + lane&15) @k0 ; lanes 16-31 same rows @k8
    // B x4: lanes 0-7 -> n rows @k0 ; 8-15 @k8 ; 16-23 rows+8 @k0 ; 24-31 rows+8 @k8
    const uint32_t aLane = (uint32_t)((wm + (lane & 15)) * ROW_BYTES + (lane >> 4) * 16);
    const uint32_t bLane = (uint32_t)((wn + (lane & 7) + ((lane >> 4) << 3)) * ROW_BYTES
                                      + ((lane >> 3) & 1) * 16) + MAT_BYTES;

    float acc[4][4][4];
#pragma unroll
    for (int a = 0; a < 4; ++a)
#pragma unroll
        for (int b = 0; b < 4; ++b)
#pragma unroll
            for (int k = 0; k < 4; ++k) acc[a][b][k] = 0.f;

    int s = 0;
    for (int i = 0; i < NCH; ++i) {
        CP_WAIT();
        __syncthreads();

        const uint32_t stA = shBase + s * STAGE_BYTES + aLane;
        const uint32_t stB = shBase + s * STAGE_BYTES + bLane;

        const int ch = i + STAGES - 1;
        const int sn = (s + STAGES - 1 >= STAGES) ? s + STAGES - 1 - STAGES : s + STAGES - 1;
        if (ch < NCH) {
#pragma unroll
            for (int q = 0; q < 8; ++q)
                cp16(sRow + sn * STAGE_BYTES + q * 16, gRow + (size_t)ch * 64 + q * 8, lSz);
        }
        CP_COMMIT();

#pragma unroll
        for (int kk = 0; kk < 4; ++kk) {           // four k16 steps per 64-half chunk
            uint32_t afr[4][4], bfr[4][2];
#pragma unroll
            for (int ma = 0; ma < 4; ++ma)
                ldsm4(afr[ma], stA + ma * 16 * ROW_BYTES + kk * 32);
#pragma unroll
            for (int nb = 0; nb < 2; ++nb) {
                uint32_t r[4];
                ldsm4(r, stB + nb * 16 * ROW_BYTES + kk * 32);
                bfr[nb * 2][0] = r[0]; bfr[nb * 2][1] = r[1];
                bfr[nb * 2 + 1][0] = r[2]; bfr[nb * 2 + 1][1] = r[3];
            }
#pragma unroll
            for (int ma = 0; ma < 4; ++ma)
#pragma unroll
                for (int na = 0; na < 4; ++na)
                    mma_bf16(acc[ma][na], afr[ma], bfr[na]);
        }
        s = (s + 1 == STAGES) ? 0 : s + 1;
    }

    // ---- fused decode epilogue ----
#pragma unroll
    for (int ma = 0; ma < 4; ++ma) {
#pragma unroll
        for (int half = 0; half < 2; ++half) {
            const int m = m0 + wm + ma * 16 + g + half * 8;
            if (m >= 267) continue;
            const int ai = m / 89;
            const int e  = m - ai * 89;
            const float bv = sBias[m];
            const float anc = (e == 2) ? g_anch[lvl][ai * 2]
                            : (e == 3) ? g_anch[lvl][ai * 2 + 1] : 0.f;
            const size_t rowbase = (size_t)bat * 25200 + (size_t)loff + (size_t)ai * HW;
#pragma unroll
            for (int na = 0; na < 4; ++na) {
#pragma unroll
                for (int c = 0; c < 2; ++c) {
                    const int n = n0 + wn + na * 8 + t4 * 2 + c;
                    if (HW % 128 != 0) { if (n >= HW) continue; }
                    const float v = acc[ma][na][half * 2 + c] + bv;
                    float res;
                    if (e == 0)      res = (sigm(v) + (float)(n % NX)) * stride_px;
                    else if (e == 1) res = (sigm(v) + (float)(n / NX)) * stride_px;
                    else if (e < 4)  res = __expf(v) * anc;
                    else             res = sigm(v);
                    Out[(rowbase + (size_t)n) * 89 + e] = res;
                }
            }
        }
    }
}

// N tiles: L0 50, L1 13 (last partial), L2 4 (last partial) -> 67
__global__ void __launch_bounds__(NTH, 2)
detect_mma(const float* __restrict__ b0, const float* __restrict__ b1,
           const float* __restrict__ b2, float* __restrict__ out)
{
    const int xt  = blockIdx.x;
    const int mt  = blockIdx.y;
    const int bat = blockIdx.z;

    if (xt < 50)
        run_level<256, 6400, 80>(g_xt, g_wb, b0, out, bat, mt, xt, 8.f, 0, 0);
    else if (xt < 63)
        run_level<512, 1600, 40>(g_xt + 13107200, g_wb + 68352, b1, out, bat, mt, xt - 50, 16.f, 1, 19200);
    else
        run_level<1024, 400, 20>(g_xt + 19660800, g_wb + 205056, b2, out, bat, mt, xt - 63, 32.f, 2, 24000);
}

extern "C" void kernel_launch(void* const* d_in, const int* in_sizes, int n_in,
                              void* d_out, int out_size)
{
    const float *x0 = 0, *x1 = 0, *x2 = 0, *w0 = 0, *w1 = 0, *w2 = 0;
    const float* bs[3] = {0, 0, 0};
    int nb = 0;
    for (int i = 0; i < n_in; ++i) {
        const float* p = (const float*)d_in[i];
        switch (in_sizes[i]) {
            case 13107200: x0 = p; break;
            case 6553600:  x1 = p; break;
            case 3276800:  x2 = p; break;
            case 68352:    w0 = p; break;
            case 136704:   w1 = p; break;
            case 273408:   w2 = p; break;
            case 267:      if (nb < 3) bs[nb++] = p; break;
            default: break;
        }
    }

    __nv_bfloat16* xt_ptr = 0;
    cudaGetSymbolAddress((void**)&xt_ptr, g_xt);

    convert_w<<<(478464 + 255) / 256, 256>>>(w0, w1, w2);
    {
        dim3 b(32, 8);
        transpose_x<256, 6400><<<dim3(200, 8, 8), b>>>(x0, xt_ptr);
        transpose_x<512, 1600><<<dim3(50, 16, 8), b>>>(x1, xt_ptr + 13107200);
        transpose_x<1024, 400><<<dim3(13, 32, 8), b>>>(x2, xt_ptr + 19660800);
    }

    cudaFuncSetAttribute(detect_mma, cudaFuncAttributeMaxDynamicSharedMemorySize, DYN_BYTES);
    dim3 grid(67, 3, 8);
    detect_mma<<<grid, NTH, DYN_BYTES>>>(bs[0], bs[1], bs[2], (float*)d_out);
}

// round 9
// speedup vs baseline: 1.0167x; 1.0167x over previous
#include <cuda_runtime.h>
#include <cuda_bf16.h>
#include <cstdint>

#define NTH 256
#define STAGES 3

// W bf16 scratch: w0@0 (68352), w1@68352 (136704), w2@205056 (273408)
__device__ __nv_bfloat16 g_wb[478464];

__constant__ float g_anch[3][6] = {
    {10.f, 13.f, 16.f, 30.f, 33.f, 23.f},
    {30.f, 61.f, 62.f, 45.f, 59.f, 119.f},
    {116.f, 90.f, 156.f, 198.f, 373.f, 326.f}
};

__device__ __forceinline__ float sigm(float x) { return 1.f / (1.f + __expf(-x)); }

__device__ __forceinline__ void mma_bf16(float* c, const uint32_t* a, const uint32_t* b) {
    asm volatile(
        "mma.sync.aligned.m16n8k16.row.col.f32.bf16.bf16.f32 "
        "{%0,%1,%2,%3}, {%4,%5,%6,%7}, {%8,%9}, {%0,%1,%2,%3};"
        : "+f"(c[0]), "+f"(c[1]), "+f"(c[2]), "+f"(c[3])
        : "r"(a[0]), "r"(a[1]), "r"(a[2]), "r"(a[3]), "r"(b[0]), "r"(b[1]));
}
__device__ __forceinline__ void ldsm4(uint32_t* r, uint32_t addr) {
    asm volatile("ldmatrix.sync.aligned.m8n8.x4.shared.b16 {%0,%1,%2,%3}, [%4];"
                 : "=r"(r[0]), "=r"(r[1]), "=r"(r[2]), "=r"(r[3]) : "r"(addr));
}
// pack two f32 -> bf16x2 (lo = first arg, hi = second)
__device__ __forceinline__ uint32_t cvt2(float lo, float hi) {
    uint32_t r;
    asm("cvt.rn.bf16x2.f32 %0, %1, %2;" : "=r"(r) : "f"(hi), "f"(lo));
    return r;
}
__device__ __forceinline__ void cp16(uint32_t saddr, const void* gptr, uint32_t sz) {
    asm volatile("cp.async.cg.shared.global [%0], [%1], 16, %2;"
                 :: "r"(saddr), "l"(gptr), "r"(sz) : "memory");
}
#define CP_COMMIT() asm volatile("cp.async.commit_group;" ::: "memory")
#define CP_WAIT()   asm volatile("cp.async.wait_group %0;" :: "n"(STAGES - 2) : "memory")

// A: bf16 [128 m][40 halves] (32 data + 8 pad) -> 80 B/row (ldmatrix phases conflict-free)
// B: fp32 [32 k][132 floats]  (128 data + 4 pad) -> 528 B/row (bank = 4k + n mod 32)
#define A_ROW_B 80
#define B_ROW_B 528
#define A_BYTES (128 * A_ROW_B)               // 10240
#define B_BYTES (32 * B_ROW_B)                // 16896
#define STAGE_BYTES (A_BYTES + B_BYTES)       // 27136
#define DYN_BYTES (STAGES * STAGE_BYTES + 1088)

// ---------------- convert W (tiny pre-pass) ----------------
__global__ void convert_w(const float* __restrict__ w0, const float* __restrict__ w1,
                          const float* __restrict__ w2)
{
    int i = blockIdx.x * 256 + threadIdx.x;
    if (i < 68352)        g_wb[i] = __float2bfloat16(w0[i]);
    else if (i < 205056)  g_wb[i] = __float2bfloat16(w1[i - 68352]);
    else if (i < 478464)  g_wb[i] = __float2bfloat16(w2[i - 205056]);
}

// ---------------- GEMM + decode ----------------
template<int C, int HW, int NX>
__device__ __forceinline__ void run_level(
    const float* __restrict__ X, const __nv_bfloat16* __restrict__ Wb,
    const float* __restrict__ Bias, float* __restrict__ Out,
    int bat, int mt, int nt, float stride_px, int lvl, int loff)
{
    extern __shared__ char sh[];
    float* sBias = (float*)(sh + STAGES * STAGE_BYTES);
    const uint32_t shBase = (uint32_t)__cvta_generic_to_shared(sh);

    const int tid  = threadIdx.x;
    const int wid  = tid >> 5;
    const int lane = tid & 31;
    const int g    = lane >> 2;
    const int t4   = lane & 3;
    const int wm   = (wid & 1) * 64;
    const int wn   = (wid >> 1) * 32;
    const int m0   = mt * 128;
    const int n0   = nt * 128;
    const float* Xb = X + (size_t)bat * C * HW;

    for (int i = tid; i < 267; i += NTH) sBias[i] = Bias[i];

    // ---- cp.async loaders ----
    // A half (tid<128): thread = one m row, 4x cp16 of bf16 (64B data)
    // B half (tid>=128): t2 = tid-128: row k = t2&31, 128B n-segment = (t2>>5)*32 floats, 8x cp16
    const bool isB = tid >= 128;
    const int t2 = tid & 127;
    // A params
    const int aRow = t2;
    const uint32_t aSz = ((m0 + aRow) < 267) ? 16u : 0u;
    const __nv_bfloat16* aG = Wb + (size_t)((m0 + aRow) < 267 ? (m0 + aRow) : 0) * C;
    const uint32_t aS = shBase + aRow * A_ROW_B;
    // B params
    const int bRow = t2 & 31;
    const int bSeg = (t2 >> 5) * 32;                     // float offset within 128-n row
    const uint32_t bS = shBase + A_BYTES + bRow * B_ROW_B + bSeg * 4;
    const float* bG = Xb + (size_t)bRow * HW + n0 + bSeg;

    const int NCH = C / 32;
#pragma unroll
    for (int s = 0; s < STAGES - 1; ++s) {
        if (s < NCH) {
            if (!isB) {
#pragma unroll
                for (int q = 0; q < 4; ++q)
                    cp16(aS + s * STAGE_BYTES + q * 16, aG + (size_t)s * 32 + q * 8, aSz);
            } else {
#pragma unroll
                for (int q = 0; q < 8; ++q) {
                    const int gn = n0 + bSeg + q * 4;
                    cp16(bS + s * STAGE_BYTES + q * 16, bG + (size_t)s * 32 * HW + q * 4,
                         (gn < HW) ? 16u : 0u);
                }
            }
        }
        CP_COMMIT();
    }

    // ldmatrix A lane address: lanes 0-15 -> rows wm+(lane&15) @k-halves 0-7,
    // lanes 16-31 -> same rows @k-halves 8-15
    const uint32_t aLane = (uint32_t)((wm + (lane & 15)) * A_ROW_B + (lane >> 4) * 16);

    float acc[4][4][4];
#pragma unroll
    for (int a = 0; a < 4; ++a)
#pragma unroll
        for (int b = 0; b < 4; ++b)
#pragma unroll
            for (int k = 0; k < 4; ++k) acc[a][b][k] = 0.f;

    int s = 0;
    for (int i = 0; i < NCH; ++i) {
        CP_WAIT();
        __syncthreads();

        const uint32_t stA = shBase + s * STAGE_BYTES + aLane;
        const float* Bst = (const float*)(sh + s * STAGE_BYTES + A_BYTES);

        const int ch = i + STAGES - 1;
        const int sn = (s + STAGES - 1 >= STAGES) ? s + STAGES - 1 - STAGES : s + STAGES - 1;
        if (ch < NCH) {
            if (!isB) {
#pragma unroll
                for (int q = 0; q < 4; ++q)
                    cp16(aS + sn * STAGE_BYTES + q * 16, aG + (size_t)ch * 32 + q * 8, aSz);
            } else {
#pragma unroll
                for (int q = 0; q < 8; ++q) {
                    const int gn = n0 + bSeg + q * 4;
                    cp16(bS + sn * STAGE_BYTES + q * 16, bG + (size_t)ch * 32 * HW + q * 4,
                         (gn < HW) ? 16u : 0u);
                }
            }
        }
        CP_COMMIT();

#pragma unroll
        for (int kk = 0; kk < 2; ++kk) {           // two k16 steps per 32-k chunk
            uint32_t afr[4][4];
#pragma unroll
            for (int ma = 0; ma < 4; ++ma)
                ldsm4(afr[ma], stA + ma * 16 * A_ROW_B + kk * 32);

            uint32_t bfr[4][2];
            const int kb = kk * 16;
#pragma unroll
            for (int na = 0; na < 4; ++na) {
                const int nc = wn + na * 8 + g;
                const float* p0 = Bst + (size_t)(kb + 2 * t4) * 132 + nc;
                bfr[na][0] = cvt2(p0[0], p0[132]);                    // k = 2t4, 2t4+1
                const float* p1 = p0 + (size_t)8 * 132;
                bfr[na][1] = cvt2(p1[0], p1[132]);                    // k = 8+2t4, +1
            }
#pragma unroll
            for (int ma = 0; ma < 4; ++ma)
#pragma unroll
                for (int na = 0; na < 4; ++na)
                    mma_bf16(acc[ma][na], afr[ma], bfr[na]);
        }
        s = (s + 1 == STAGES) ? 0 : s + 1;
    }

    // ---- fused decode epilogue ----
#pragma unroll
    for (int ma = 0; ma < 4; ++ma) {
#pragma unroll
        for (int half = 0; half < 2; ++half) {
            const int m = m0 + wm + ma * 16 + g + half * 8;
            if (m >= 267) continue;
            const int ai = m / 89;
            const int e  = m - ai * 89;
            const float bv = sBias[m];
            const float anc = (e == 2) ? g_anch[lvl][ai * 2]
                            : (e == 3) ? g_anch[lvl][ai * 2 + 1] : 0.f;
            const size_t rowbase = (size_t)bat * 25200 + (size_t)loff + (size_t)ai * HW;
#pragma unroll
            for (int na = 0; na < 4; ++na) {
#pragma unroll
                for (int c = 0; c < 2; ++c) {
                    const int n = n0 + wn + na * 8 + t4 * 2 + c;
                    if (HW % 128 != 0) { if (n >= HW) continue; }
                    const float v = acc[ma][na][half * 2 + c] + bv;
                    float res;
                    if (e == 0)      res = (sigm(v) + (float)(n % NX)) * stride_px;
                    else if (e == 1) res = (sigm(v) + (float)(n / NX)) * stride_px;
                    else if (e < 4)  res = __expf(v) * anc;
                    else             res = sigm(v);
                    Out[(rowbase + (size_t)n) * 89 + e] = res;
                }
            }
        }
    }
}

// N tiles: L0 50, L1 13 (last partial), L2 4 (last partial) -> 67
__global__ void __launch_bounds__(NTH, 2)
detect_mma(const float* __restrict__ x0, const float* __restrict__ x1,
           const float* __restrict__ x2,
           const float* __restrict__ b0, const float* __restrict__ b1,
           const float* __restrict__ b2, float* __restrict__ out)
{
    const int xt  = blockIdx.x;
    const int mt  = blockIdx.y;
    const int bat = blockIdx.z;

    if (xt < 50)
        run_level<256, 6400, 80>(x0, g_wb, b0, out, bat, mt, xt, 8.f, 0, 0);
    else if (xt < 63)
        run_level<512, 1600, 40>(x1, g_wb + 68352, b1, out, bat, mt, xt - 50, 16.f, 1, 19200);
    else
        run_level<1024, 400, 20>(x2, g_wb + 205056, b2, out, bat, mt, xt - 63, 32.f, 2, 24000);
}

extern "C" void kernel_launch(void* const* d_in, const int* in_sizes, int n_in,
                              void* d_out, int out_size)
{
    const float *x0 = 0, *x1 = 0, *x2 = 0, *w0 = 0, *w1 = 0, *w2 = 0;
    const float* bs[3] = {0, 0, 0};
    int nb = 0;
    for (int i = 0; i < n_in; ++i) {
        const float* p = (const float*)d_in[i];
        switch (in_sizes[i]) {
            case 13107200: x0 = p; break;
            case 6553600:  x1 = p; break;
            case 3276800:  x2 = p; break;
            case 68352:    w0 = p; break;
            case 136704:   w1 = p; break;
            case 273408:   w2 = p; break;
            case 267:      if (nb < 3) bs[nb++] = p; break;
            default: break;
        }
    }

    convert_w<<<(478464 + 255) / 256, 256>>>(w0, w1, w2);

    cudaFuncSetAttribute(detect_mma, cudaFuncAttributeMaxDynamicSharedMemorySize, DYN_BYTES);
    dim3 grid(67, 3, 8);
    detect_mma<<<grid, NTH, DYN_BYTES>>>(x0, x1, x2, bs[0], bs[1], bs[2], (float*)d_out);
}

// round 10
// speedup vs baseline: 1.1515x; 1.1325x over previous
#include <cuda_runtime.h>
#include <cuda_bf16.h>
#include <cstdint>

#define NTH 256
#define STAGES 3

// W bf16 scratch: w0@0 (68352), w1@68352 (136704), w2@205056 (273408)
__device__ __nv_bfloat16 g_wb[478464];

__constant__ float g_anch[3][6] = {
    {10.f, 13.f, 16.f, 30.f, 33.f, 23.f},
    {30.f, 61.f, 62.f, 45.f, 59.f, 119.f},
    {116.f, 90.f, 156.f, 198.f, 373.f, 326.f}
};

__device__ __forceinline__ float sigm(float x) { return 1.f / (1.f + __expf(-x)); }

__device__ __forceinline__ void mma_bf16(float* c, const uint32_t* a, const uint32_t* b) {
    asm volatile(
        "mma.sync.aligned.m16n8k16.row.col.f32.bf16.bf16.f32 "
        "{%0,%1,%2,%3}, {%4,%5,%6,%7}, {%8,%9}, {%0,%1,%2,%3};"
        : "+f"(c[0]), "+f"(c[1]), "+f"(c[2]), "+f"(c[3])
        : "r"(a[0]), "r"(a[1]), "r"(a[2]), "r"(a[3]), "r"(b[0]), "r"(b[1]));
}
__device__ __forceinline__ void ldsm4(uint32_t* r, uint32_t addr) {
    asm volatile("ldmatrix.sync.aligned.m8n8.x4.shared.b16 {%0,%1,%2,%3}, [%4];"
                 : "=r"(r[0]), "=r"(r[1]), "=r"(r[2]), "=r"(r[3]) : "r"(addr));
}
__device__ __forceinline__ uint32_t cvt2(float lo, float hi) {
    uint32_t r;
    asm("cvt.rn.bf16x2.f32 %0, %1, %2;" : "=r"(r) : "f"(hi), "f"(lo));
    return r;
}
__device__ __forceinline__ void cp16(uint32_t saddr, const void* gptr, uint32_t sz) {
    asm volatile("cp.async.cg.shared.global [%0], [%1], 16, %2;"
                 :: "r"(saddr), "l"(gptr), "r"(sz) : "memory");
}
#define CP_COMMIT() asm volatile("cp.async.commit_group;" ::: "memory")
#define CP_WAIT()   asm volatile("cp.async.wait_group %0;" :: "n"(STAGES - 2) : "memory")

// CTA tile: 128 M x 64 N.  A: bf16 [128 m][40 halves] (32 data + 8 pad) = 80 B/row.
// B: fp32 [32 k][68 floats] (64 data + 4 pad) = 272 B/row.
#define A_ROW_B 80
#define B_ROW_F 68
#define A_BYTES (128 * A_ROW_B)               // 10240
#define B_BYTES (32 * B_ROW_F * 4)            // 8704
#define STAGE_BYTES (A_BYTES + B_BYTES)       // 18944
#define DYN_BYTES (STAGES * STAGE_BYTES + 1088)
// epilogue transpose buffer Pt[64 n][132 m-floats] = 33792 B (reuses stage buffers)
#define PT_STRIDE 132

__global__ void convert_w(const float* __restrict__ w0, const float* __restrict__ w1,
                          const float* __restrict__ w2)
{
    int i = blockIdx.x * 256 + threadIdx.x;
    if (i < 68352)        g_wb[i] = __float2bfloat16(w0[i]);
    else if (i < 205056)  g_wb[i] = __float2bfloat16(w1[i - 68352]);
    else if (i < 478464)  g_wb[i] = __float2bfloat16(w2[i - 205056]);
}

template<int C, int HW, int NX>
__device__ __forceinline__ void run_level(
    const float* __restrict__ X, const __nv_bfloat16* __restrict__ Wb,
    const float* __restrict__ Bias, float* __restrict__ Out,
    int bat, int mt, int nt, float stride_px, int lvl, int loff)
{
    extern __shared__ char sh[];
    float* sBias = (float*)(sh + STAGES * STAGE_BYTES);
    float* Pt = (float*)sh;
    const uint32_t shBase = (uint32_t)__cvta_generic_to_shared(sh);

    const int tid  = threadIdx.x;
    const int wid  = tid >> 5;
    const int lane = tid & 31;
    const int g    = lane >> 2;
    const int t4   = lane & 3;
    const int wm   = (wid & 3) * 32;     // 4 warps along M
    const int wn   = (wid >> 2) * 32;    // 2 warps along N
    const int m0   = mt * 128;
    const int n0   = nt * 64;
    const float* Xb = X + (size_t)bat * C * HW;

    for (int i = tid; i < 267; i += NTH) sBias[i] = Bias[i];

    // ---- cp.async loaders: threads 0-127 -> A (1 m-row, 4x cp16), 128-255 -> B ----
    const bool isB = tid >= 128;
    const int t2 = tid & 127;
    const uint32_t aSz = ((m0 + t2) < 267) ? 16u : 0u;
    const __nv_bfloat16* aG = Wb + (size_t)((m0 + t2) < 267 ? (m0 + t2) : 0) * C;
    const uint32_t aS = shBase + t2 * A_ROW_B;
    const int bK = t2 >> 2;                 // k row 0..31
    const int bSeg = (t2 & 3) * 16;         // float offset 0/16/32/48
    const uint32_t bS = shBase + A_BYTES + (bK * B_ROW_F + bSeg) * 4;
    const float* bG = Xb + (size_t)bK * HW + n0 + bSeg;

    const int NCH = C / 32;
#pragma unroll
    for (int s = 0; s < STAGES - 1; ++s) {
        if (s < NCH) {
            if (!isB) {
#pragma unroll
                for (int q = 0; q < 4; ++q)
                    cp16(aS + s * STAGE_BYTES + q * 16, aG + (size_t)s * 32 + q * 8, aSz);
            } else {
#pragma unroll
                for (int q = 0; q < 4; ++q) {
                    const int gn = n0 + bSeg + q * 4;
                    cp16(bS + s * STAGE_BYTES + q * 16, bG + (size_t)s * 32 * HW + q * 4,
                         (gn < HW) ? 16u : 0u);
                }
            }
        }
        CP_COMMIT();
    }

    const uint32_t aLane = (uint32_t)((wm + (lane & 15)) * A_ROW_B + (lane >> 4) * 16);

    float acc[2][4][4];
#pragma unroll
    for (int a = 0; a < 2; ++a)
#pragma unroll
        for (int b = 0; b < 4; ++b)
#pragma unroll
            for (int k = 0; k < 4; ++k) acc[a][b][k] = 0.f;

    int s = 0;
    for (int i = 0; i < NCH; ++i) {
        CP_WAIT();
        __syncthreads();

        const uint32_t stA = shBase + s * STAGE_BYTES + aLane;
        const float* Bst = (const float*)(sh + s * STAGE_BYTES + A_BYTES);

        const int ch = i + STAGES - 1;
        const int sn = (s + STAGES - 1 >= STAGES) ? s + STAGES - 1 - STAGES : s + STAGES - 1;
        if (ch < NCH) {
            if (!isB) {
#pragma unroll
                for (int q = 0; q < 4; ++q)
                    cp16(aS + sn * STAGE_BYTES + q * 16, aG + (size_t)ch * 32 + q * 8, aSz);
            } else {
#pragma unroll
                for (int q = 0; q < 4; ++q) {
                    const int gn = n0 + bSeg + q * 4;
                    cp16(bS + sn * STAGE_BYTES + q * 16, bG + (size_t)ch * 32 * HW + q * 4,
                         (gn < HW) ? 16u : 0u);
                }
            }
        }
        CP_COMMIT();

#pragma unroll
        for (int kk = 0; kk < 2; ++kk) {
            uint32_t afr[2][4];
#pragma unroll
            for (int ma = 0; ma < 2; ++ma)
                ldsm4(afr[ma], stA + ma * 16 * A_ROW_B + kk * 32);

            uint32_t bfr[4][2];
            const int kb = kk * 16;
#pragma unroll
            for (int na = 0; na < 4; ++na) {
                const int nc = wn + na * 8 + g;
                const float* p0 = Bst + (size_t)(kb + 2 * t4) * B_ROW_F + nc;
                bfr[na][0] = cvt2(p0[0], p0[B_ROW_F]);
                const float* p1 = p0 + (size_t)8 * B_ROW_F;
                bfr[na][1] = cvt2(p1[0], p1[B_ROW_F]);
            }
#pragma unroll
            for (int ma = 0; ma < 2; ++ma)
#pragma unroll
                for (int na = 0; na < 4; ++na)
                    mma_bf16(acc[ma][na], afr[ma], bfr[na]);
        }
        s = (s + 1 == STAGES) ? 0 : s + 1;
    }

    // ---- epilogue phase 1: transpose acc -> Pt[n][m] (conflict-free STS) ----
    __syncthreads();   // all warps done reading stage buffers
#pragma unroll
    for (int ma = 0; ma < 2; ++ma)
#pragma unroll
        for (int h = 0; h < 2; ++h) {
            const int ml = wm + ma * 16 + g + h * 8;
#pragma unroll
            for (int na = 0; na < 4; ++na)
#pragma unroll
                for (int c = 0; c < 2; ++c) {
                    const int nl = wn + na * 8 + t4 * 2 + c;
                    Pt[nl * PT_STRIDE + ml] = acc[ma][na][h * 2 + c];
                }
        }
    __syncthreads();

    // ---- epilogue phase 2: coalesced decode+store (lanes along m -> e) ----
#pragma unroll
    for (int i = 0; i < 8; ++i) {
        const int nl = wid * 8 + i;
        const int n = n0 + nl;
        if (n >= HW) break;
        const float gx = (float)(n % NX);
        const float gy = (float)(n / NX);
        const size_t obase = ((size_t)bat * 25200 + loff + n) * 89;
#pragma unroll
        for (int p = 0; p < 4; ++p) {
            const int lm = p * 32 + lane;
            const int m = m0 + lm;
            if (m < 267) {
                const int ai = m / 89;
                const int e  = m - ai * 89;
                const float v = Pt[nl * PT_STRIDE + lm] + sBias[m];
                float res;
                if (e == 0)      res = (sigm(v) + gx) * stride_px;
                else if (e == 1) res = (sigm(v) + gy) * stride_px;
                else if (e < 4)  res = __expf(v) * g_anch[lvl][ai * 2 + (e - 2)];
                else             res = sigm(v);
                Out[obase + (size_t)ai * HW * 89 + e] = res;
            }
        }
    }
}

// N tiles (64-wide): L0 100, L1 25, L2 7 -> 132
__global__ void __launch_bounds__(NTH, 3)
detect_mma(const float* __restrict__ x0, const float* __restrict__ x1,
           const float* __restrict__ x2,
           const float* __restrict__ b0, const float* __restrict__ b1,
           const float* __restrict__ b2, float* __restrict__ out)
{
    const int xt  = blockIdx.x;
    const int mt  = blockIdx.y;
    const int bat = blockIdx.z;

    if (xt < 100)
        run_level<256, 6400, 80>(x0, g_wb, b0, out, bat, mt, xt, 8.f, 0, 0);
    else if (xt < 125)
        run_level<512, 1600, 40>(x1, g_wb + 68352, b1, out, bat, mt, xt - 100, 16.f, 1, 19200);
    else
        run_level<1024, 400, 20>(x2, g_wb + 205056, b2, out, bat, mt, xt - 125, 32.f, 2, 24000);
}

extern "C" void kernel_launch(void* const* d_in, const int* in_sizes, int n_in,
                              void* d_out, int out_size)
{
    const float *x0 = 0, *x1 = 0, *x2 = 0, *w0 = 0, *w1 = 0, *w2 = 0;
    const float* bs[3] = {0, 0, 0};
    int nb = 0;
    for (int i = 0; i < n_in; ++i) {
        const float* p = (const float*)d_in[i];
        switch (in_sizes[i]) {
            case 13107200: x0 = p; break;
            case 6553600:  x1 = p; break;
            case 3276800:  x2 = p; break;
            case 68352:    w0 = p; break;
            case 136704:   w1 = p; break;
            case 273408:   w2 = p; break;
            case 267:      if (nb < 3) bs[nb++] = p; break;
            default: break;
        }
    }

    convert_w<<<(478464 + 255) / 256, 256>>>(w0, w1, w2);

    cudaFuncSetAttribute(detect_mma, cudaFuncAttributeMaxDynamicSharedMemorySize, DYN_BYTES);
    dim3 grid(132, 3, 8);
    detect_mma<<<grid, NTH, DYN_BYTES>>>(x0, x1, x2, bs[0], bs[1], bs[2], (float*)d_out);
}